// round 17
// baseline (speedup 1.0000x reference)
#include <cuda_runtime.h>
#include <cuda_bf16.h>
#include <cuda_fp16.h>
#include <cstdint>
#include <math.h>

// ---------------- problem constants ----------------
#define BB 16
#define SS 1024
#define DD 1024
#define HH 8
#define QKD 128
#define EXPD 2048
#define NROWS (BB*SS)    // 16384
#define EOUT (2*QKD + 2*EXPD)  // 4352
#define LOG2E 1.4426950408889634f

// ---------------- scratch ----------------
__device__ __nv_bfloat16 g_xn[(size_t)NROWS * DD];
__device__ __nv_bfloat16 g_qk[(size_t)NROWS * 256];       // [q(128, pre-scaled by 0.25*log2e) | k(128)]
__device__ __nv_bfloat16 g_concat[(size_t)NROWS * EXPD];  // [0,1024): geglu_local, [1024,2048): attention
__device__ __half g_v[(size_t)NROWS * DD];                // V in f16
__device__ __nv_bfloat16 g_wexp[(size_t)EOUT * DD];       // reordered: [q,k | interleaved lin/pre]
__device__ __nv_bfloat16 g_wproj[(size_t)DD * EXPD];

// ---------------- helpers ----------------
__device__ __forceinline__ void mma16816(float d[4], const uint32_t a[4], const uint32_t b[2]) {
    asm volatile(
        "mma.sync.aligned.m16n8k16.row.col.f32.bf16.bf16.f32 "
        "{%0,%1,%2,%3},{%4,%5,%6,%7},{%8,%9},{%0,%1,%2,%3};\n"
        : "+f"(d[0]), "+f"(d[1]), "+f"(d[2]), "+f"(d[3])
        : "r"(a[0]), "r"(a[1]), "r"(a[2]), "r"(a[3]), "r"(b[0]), "r"(b[1]));
}

__device__ __forceinline__ void mma16816h(float d[4], const uint32_t a[4], const uint32_t b[2]) {
    asm volatile(
        "mma.sync.aligned.m16n8k16.row.col.f32.f16.f16.f32 "
        "{%0,%1,%2,%3},{%4,%5,%6,%7},{%8,%9},{%0,%1,%2,%3};\n"
        : "+f"(d[0]), "+f"(d[1]), "+f"(d[2]), "+f"(d[3])
        : "r"(a[0]), "r"(a[1]), "r"(a[2]), "r"(a[3]), "r"(b[0]), "r"(b[1]));
}

__device__ __forceinline__ void ldsm4(uint32_t r[4], uint32_t saddr) {
    asm volatile("ldmatrix.sync.aligned.m8n8.x4.shared.b16 {%0,%1,%2,%3}, [%4];"
                 : "=r"(r[0]), "=r"(r[1]), "=r"(r[2]), "=r"(r[3]) : "r"(saddr));
}

__device__ __forceinline__ void ldsm4t(uint32_t r[4], uint32_t saddr) {
    asm volatile("ldmatrix.sync.aligned.m8n8.x4.trans.shared.b16 {%0,%1,%2,%3}, [%4];"
                 : "=r"(r[0]), "=r"(r[1]), "=r"(r[2]), "=r"(r[3]) : "r"(saddr));
}

__device__ __forceinline__ void cp16(uint32_t saddr, const void* g) {
    asm volatile("cp.async.cg.shared.global [%0], [%1], 16;" :: "r"(saddr), "l"(g));
}

// pack two f32 -> f16x2 (lo in low half)
__device__ __forceinline__ __half2 packh2(float lo, float hi) {
    __half2 r;
    asm("cvt.rn.f16x2.f32 %0, %1, %2;" : "=r"(*(uint32_t*)&r) : "f"(hi), "f"(lo));
    return r;
}

__device__ __forceinline__ float gelu_exact(float p) {
    return 0.5f * p * (1.f + erff(p * 0.70710678118654752f));
}

// ---------------- merged weight convert (wexp reorder + wproj) ----------------
#define WEXP4 (EOUT * DD / 4)      // 1114112
#define WPROJ4 (DD * EXPD / 4)     // 524288
__global__ void cvt_all_kernel(const float* __restrict__ expand_w,
                               const float* __restrict__ project_w,
                               __nv_bfloat16* __restrict__ wexp,
                               __nv_bfloat16* __restrict__ wproj) {
    int i = blockIdx.x * blockDim.x + threadIdx.x;
    if (i < WEXP4) {
        int r = i >> 8;
        int c4 = i & 255;
        int t = r - 256;
        int sr = (r < 256) ? r : ((t & 1) ? (2304 + (t >> 1)) : (256 + (t >> 1)));
        float4 v = ((const float4*)(expand_w + (size_t)sr * DD))[c4];
        __nv_bfloat162* d = (__nv_bfloat162*)(wexp + (size_t)r * DD + c4 * 4);
        d[0] = __floats2bfloat162_rn(v.x, v.y);
        d[1] = __floats2bfloat162_rn(v.z, v.w);
    } else {
        int j = i - WEXP4;
        if (j < WPROJ4) {
            float4 v = ((const float4*)project_w)[j];
            __nv_bfloat162* d = (__nv_bfloat162*)(wproj + (size_t)j * 4);
            d[0] = __floats2bfloat162_rn(v.x, v.y);
            d[1] = __floats2bfloat162_rn(v.z, v.w);
        }
    }
}

// ---------------- LayerNorm ----------------
__global__ __launch_bounds__(256) void ln_kernel(const float* __restrict__ x,
                                                 const float* __restrict__ w,
                                                 __nv_bfloat16* __restrict__ out) {
    int row = blockIdx.x;
    float4 v = ((const float4*)(x + (size_t)row * DD))[threadIdx.x];
    float s = v.x + v.y + v.z + v.w;
    float s2 = v.x * v.x + v.y * v.y + v.z * v.z + v.w * v.w;
#pragma unroll
    for (int o = 16; o; o >>= 1) {
        s += __shfl_xor_sync(0xffffffffu, s, o);
        s2 += __shfl_xor_sync(0xffffffffu, s2, o);
    }
    __shared__ float rs[8], rs2[8];
    int warp = threadIdx.x >> 5, lane = threadIdx.x & 31;
    if (!lane) { rs[warp] = s; rs2[warp] = s2; }
    __syncthreads();
    if (threadIdx.x == 0) {
        float a = 0.f, b = 0.f;
#pragma unroll
        for (int i = 0; i < 8; i++) { a += rs[i]; b += rs2[i]; }
        rs[0] = a; rs2[0] = b;
    }
    __syncthreads();
    float mu = rs[0] * (1.f / DD);
    float var = rs2[0] * (1.f / DD) - mu * mu;
    float r = rsqrtf(var + 1e-5f);
    float4 w4 = ((const float4*)w)[threadIdx.x];
    __nv_bfloat16* op = out + (size_t)row * DD + threadIdx.x * 4;
    *(__nv_bfloat162*)op = __floats2bfloat162_rn((v.x - mu) * r * w4.x, (v.y - mu) * r * w4.y);
    *(__nv_bfloat162*)(op + 2) = __floats2bfloat162_rn((v.z - mu) * r * w4.z, (v.w - mu) * r * w4.w);
}

// ---------------- bf16 GEMM (round-16 best, unchanged) ----------------
#define GSTG 3
#define GSTAGE_BYTES (128 * 64 * 2)
#define GSMEM_BYTES (2 * GSTG * GSTAGE_BYTES)

template <int MODE, int KK>
__global__ __launch_bounds__(256, 2) void gemm_bf16(const __nv_bfloat16* __restrict__ A,
                                                    const __nv_bfloat16* __restrict__ Bw,
                                                    __nv_bfloat16* __restrict__ qk,
                                                    __nv_bfloat16* __restrict__ concat,
                                                    __half* __restrict__ vbuf,
                                                    const float* __restrict__ resid,
                                                    float* __restrict__ Cf) {
    extern __shared__ __nv_bfloat16 smbuf[];
    const int tid = threadIdx.x;
    const int warp = tid >> 5, lane = tid & 31;
    const int gid = lane >> 2, tig = lane & 3;
    const int wm = (warp >> 2) * 64, wn = (warp & 3) * 32;
    const int bm = blockIdx.y, bn = blockIdx.x;

    const uint32_t sbase = (uint32_t)__cvta_generic_to_shared(smbuf);

    const int r = tid >> 3, c = tid & 7;
    const int swz = (c ^ (r & 7)) * 16;
    const __nv_bfloat16* Ag = A + ((size_t)(bm * 128 + r)) * KK + c * 8;
    const __nv_bfloat16* Bg = Bw + ((size_t)(bn * 128 + r)) * KK + c * 8;

    uint32_t stA[GSTG], stB[GSTG];
#pragma unroll
    for (int s = 0; s < GSTG; s++) {
        stA[s] = sbase + s * GSTAGE_BYTES + r * 128 + swz;
        stB[s] = stA[s] + GSTG * GSTAGE_BYTES;
    }

    auto load_stage = [&](int s, int kt) {
        const __nv_bfloat16* ag = Ag + kt * 64;
        const __nv_bfloat16* bg = Bg + kt * 64;
#pragma unroll
        for (int it = 0; it < 4; it++) {
            cp16(stA[s] + it * 32 * 128, ag + (size_t)(it * 32) * KK);
            cp16(stB[s] + it * 32 * 128, bg + (size_t)(it * 32) * KK);
        }
    };

    float acc[4][4][4];
#pragma unroll
    for (int i = 0; i < 4; i++)
#pragma unroll
        for (int j = 0; j < 4; j++)
#pragma unroll
            for (int q = 0; q < 4; q++) acc[i][j][q] = 0.f;

    load_stage(0, 0);
    asm volatile("cp.async.commit_group;" ::: "memory");
    load_stage(1, 1);
    asm volatile("cp.async.commit_group;" ::: "memory");

    const int a_lrow = lane & 15;
    const int a_chi = lane >> 4;
    const int b_lrow = (lane & 7) + ((lane >> 4) << 3);
    const int b_chi = (lane >> 3) & 1;

    constexpr int KT = KK >> 6;
    int cur = 0, ns = 2;
    const __nv_bfloat16* pag = Ag + 2 * 64;
    const __nv_bfloat16* pbg = Bg + 2 * 64;
#pragma unroll 1
    for (int kt = 0; kt < KT; kt++) {
        asm volatile("cp.async.wait_group 1;" ::: "memory");
        __syncthreads();

        const bool pf = (kt + 2 < KT);
        const uint32_t pa_s = stA[ns];
        const uint32_t pb_s = stB[ns];

        const uint32_t sA = sbase + cur * GSTAGE_BYTES;
        const uint32_t sB = sA + GSTG * GSTAGE_BYTES;
#pragma unroll
        for (int ks = 0; ks < 4; ks++) {
            uint32_t af[4][4], bfr[4][2];
#pragma unroll
            for (int mi = 0; mi < 4; mi++) {
                int row = wm + mi * 16 + a_lrow;
                int cc = ks * 2 + a_chi;
                ldsm4(af[mi], sA + row * 128 + ((cc ^ (row & 7)) * 16));
            }
#pragma unroll
            for (int j = 0; j < 2; j++) {
                int row = wn + j * 16 + b_lrow;
                int cc = ks * 2 + b_chi;
                uint32_t rr[4];
                ldsm4(rr, sB + row * 128 + ((cc ^ (row & 7)) * 16));
                bfr[j * 2][0] = rr[0]; bfr[j * 2][1] = rr[1];
                bfr[j * 2 + 1][0] = rr[2]; bfr[j * 2 + 1][1] = rr[3];
            }
            if (pf) {
                cp16(pa_s + ks * 32 * 128, pag + (size_t)(ks * 32) * KK);
                cp16(pb_s + ks * 32 * 128, pbg + (size_t)(ks * 32) * KK);
            }
#pragma unroll
            for (int mi = 0; mi < 4; mi++)
#pragma unroll
                for (int ni = 0; ni < 4; ni++) mma16816(acc[mi][ni], af[mi], bfr[ni]);
        }
        asm volatile("cp.async.commit_group;" ::: "memory");
        pag += 64; pbg += 64;
        cur = (cur == GSTG - 1) ? 0 : cur + 1;
        ns = (ns == GSTG - 1) ? 0 : ns + 1;
    }

    const float QSCALE = 0.25f * LOG2E;
#pragma unroll
    for (int mi = 0; mi < 4; mi++) {
        int r0 = bm * 128 + wm + mi * 16 + gid;
#pragma unroll
        for (int ni = 0; ni < 4; ni++) {
            int col = bn * 128 + wn + ni * 8 + tig * 2;
            if (MODE == 1) {
                size_t i0 = (size_t)r0 * DD + col;
                size_t i1 = (size_t)(r0 + 8) * DD + col;
                float2 v0 = make_float2(acc[mi][ni][0] + resid[i0], acc[mi][ni][1] + resid[i0 + 1]);
                float2 v1 = make_float2(acc[mi][ni][2] + resid[i1], acc[mi][ni][3] + resid[i1 + 1]);
                *(float2*)&Cf[i0] = v0;
                *(float2*)&Cf[i1] = v1;
            } else {
                if (bn < 2) {
                    float f = (bn == 0) ? QSCALE : 1.f;
                    *(__nv_bfloat162*)&qk[(size_t)r0 * 256 + col] =
                        __floats2bfloat162_rn(acc[mi][ni][0] * f, acc[mi][ni][1] * f);
                    *(__nv_bfloat162*)&qk[(size_t)(r0 + 8) * 256 + col] =
                        __floats2bfloat162_rn(acc[mi][ni][2] * f, acc[mi][ni][3] * f);
                } else {
                    int e = (col - 256) >> 1;
                    float v0 = acc[mi][ni][0] * gelu_exact(acc[mi][ni][1]);
                    float v1 = acc[mi][ni][2] * gelu_exact(acc[mi][ni][3]);
                    if (e < 1024) {
                        concat[(size_t)r0 * EXPD + e] = __float2bfloat16(v0);
                        concat[(size_t)(r0 + 8) * EXPD + e] = __float2bfloat16(v1);
                    } else {
                        vbuf[(size_t)r0 * DD + e - 1024] = __float2half(v0);
                        vbuf[(size_t)(r0 + 8) * DD + e - 1024] = __float2half(v1);
                    }
                }
            }
        }
    }
}

// ---------------- flash attention: q-tile 128, 128 threads (4 warps, 32 q-rows/warp), occ 2 ----
// f16 shift-softmax, f16 PV with V-fragment reuse across the warp's two A-tiles.
#define AKS_B 6144                         // Ks stage: 128 rows * 48B
#define AVS_B 32768                        // Vs stage: 128 rows * 256B
#define AST_B (AKS_B + AVS_B)
#define ATT_SMEM (2 * AST_B)               // 77824 -> 2 CTAs/SM (smem 155.6KB, regs <=256)

__global__ __launch_bounds__(128, 2) void attn_kernel(const __nv_bfloat16* __restrict__ qk,
                                                      const __half* __restrict__ vbuf,
                                                      __nv_bfloat16* __restrict__ concat,
                                                      const float* __restrict__ pbm_p,
                                                      const int* __restrict__ fi_p,
                                                      const int* __restrict__ li_p) {
    extern __shared__ __align__(16) char asmem[];
    const int tid = threadIdx.x, warp = tid >> 5, lane = tid & 31;
    const int gid = lane >> 2, tig = lane & 3;
    const int bh = blockIdx.y, b = bh >> 3, h = bh & 7;
    const int qbase = blockIdx.x * 128;
    float pbm = *pbm_p;
    const float sp_l2 = (fmaxf(pbm, 0.f) + log1pf(expf(-fabsf(pbm)))) * LOG2E;
    int fi = *fi_p; if (fi >= SS) fi = 0;
    int li = *li_p; if (li >= SS) li = 0;

    const uint32_t abase = (uint32_t)__cvta_generic_to_shared(asmem);

    // warp covers 32 q-rows: two m16 A-tiles
    const int i0 = qbase + warp * 32 + gid;   // tile0 rows i0, i0+8
    const int i1 = i0 + 8;
    const int i2 = i0 + 16;                   // tile1 rows i2, i2+8
    const int i3 = i0 + 24;
    uint32_t qa0[4], qa1[4];
    {
        const size_t base = ((size_t)(b * SS + i0)) * 256 + h * 16 + tig * 2;
        qa0[0] = *(const uint32_t*)&qk[base];
        qa0[1] = *(const uint32_t*)&qk[base + 8 * 256];
        qa0[2] = *(const uint32_t*)&qk[base + 8];
        qa0[3] = *(const uint32_t*)&qk[base + 8 * 256 + 8];
        const size_t base1 = base + (size_t)16 * 256;
        qa1[0] = *(const uint32_t*)&qk[base1];
        qa1[1] = *(const uint32_t*)&qk[base1 + 8 * 256];
        qa1[2] = *(const uint32_t*)&qk[base1 + 8];
        qa1[3] = *(const uint32_t*)&qk[base1 + 8 * 256 + 8];
    }
    float m0 = -1e30f, m1 = -1e30f, m2 = -1e30f, m3 = -1e30f;
    float o0[16][4], o1[16][4];
#pragma unroll
    for (int ni = 0; ni < 16; ni++)
#pragma unroll
        for (int r = 0; r < 4; r++) { o0[ni][r] = 0.f; o1[ni][r] = 0.f; }
    float ol0[4] = {0.f, 0.f, 0.f, 0.f};
    float ol1[4] = {0.f, 0.f, 0.f, 0.f};

    const int qmax = qbase + 127;
    const int l15 = lane & 15, lhi = lane >> 4;
    const int kb = (lane & 7) + ((lane >> 4) << 3);
    const int kcc = (lane >> 3) & 1;

    int list[8];
    int n = 0;
#pragma unroll
    for (int kc = 0; kc < 8; kc++) {
        int kmin = kc * 128;
        if (kmin <= qmax || ((qmax >= fi) && (kmin + 127 >= li))) list[n++] = kc;
    }

    // 128 threads: each thread loads one K row (2x16B) + one V row (16x16B)
    auto load_chunk = [&](int st, int kmin) {
        uint32_t ks = abase + st * AST_B;
        uint32_t vs = ks + AKS_B;
        const __nv_bfloat16* ksrc = &qk[((size_t)(b * SS + kmin + tid)) * 256 + 128 + h * 16];
        cp16(ks + tid * 48, ksrc);
        cp16(ks + tid * 48 + 16, ksrc + 8);
        const __half* vsrc = &vbuf[((size_t)(b * SS + kmin + tid)) * DD + h * 128];
        uint32_t drow = vs + tid * 256;
        int rsw = tid & 15;
#pragma unroll
        for (int j = 0; j < 16; j++)
            cp16(drow + ((j ^ rsw) << 4), vsrc + j * 8);
    };

    const uint32_t bones[2] = {0x3C003C00u, 0x3C003C00u};  // f16 ones

    load_chunk(0, list[0] * 128);
    asm volatile("cp.async.commit_group;" ::: "memory");

    for (int t = 0; t < n; t++) {
        const int kmin = list[t] * 128;
        const int st = t & 1;
        if (t + 1 < n) {
            load_chunk((t + 1) & 1, list[t + 1] * 128);
            asm volatile("cp.async.commit_group;" ::: "memory");
            asm volatile("cp.async.wait_group 1;" ::: "memory");
        } else {
            asm volatile("cp.async.wait_group 0;" ::: "memory");
        }
        __syncthreads();

        const uint32_t ksb = abase + st * AST_B;
        const uint32_t vsb = ksb + AKS_B;
        const int km127 = kmin + 127;

        // per-row visible-j maximum (mask structure only)
        const bool fast = (km127 < qbase);
        const bool covr = (km127 >= li);
        int jm0, jm1, jm2, jm3;
        if (fast) { jm0 = jm1 = jm2 = jm3 = km127; }
        else {
            jm0 = ((i0 >= fi) && covr) ? km127 : min(i0, km127);
            jm1 = ((i1 >= fi) && covr) ? km127 : min(i1, km127);
            jm2 = ((i2 >= fi) && covr) ? km127 : min(i2, km127);
            jm3 = ((i3 >= fi) && covr) ? km127 : min(i3, km127);
        }
        const float off0 = sp_l2 * (float)(jm0 - i0);
        const float off1 = sp_l2 * (float)(jm1 - i1);
        const float off2 = sp_l2 * (float)(jm2 - i2);
        const float off3 = sp_l2 * (float)(jm3 - i3);

        // QK^T for both A-tiles with immediate bias/mask + f16x2 pack
        __half2 pA0[16], pA1[16], pB0[16], pB1[16];
#pragma unroll
        for (int ni2 = 0; ni2 < 8; ni2++) {
            uint32_t rr[4];
            ldsm4(rr, ksb + (ni2 * 16 + kb) * 48 + kcc * 16);
#pragma unroll
            for (int tt = 0; tt < 2; tt++) {
                const int ni = 2 * ni2 + tt;
                uint32_t bf[2] = {rr[2 * tt], rr[2 * tt + 1]};
                float d[4] = {0.f, 0.f, 0.f, 0.f};
                float e[4] = {0.f, 0.f, 0.f, 0.f};
                mma16816(d, qa0, bf);
                mma16816(e, qa1, bf);
                const int jc = kmin + ni * 8 + tig * 2;
                if (fast) {
                    float bb = sp_l2 * (float)(jc - km127);
                    d[0] += bb; d[1] += bb + sp_l2; d[2] += bb; d[3] += bb + sp_l2;
                    e[0] += bb; e[1] += bb + sp_l2; e[2] += bb; e[3] += bb + sp_l2;
                } else {
#pragma unroll
                    for (int rr2 = 0; rr2 < 4; rr2++) {
                        int j = jc + (rr2 & 1);
                        int ia = (rr2 < 2) ? i0 : i1;
                        int ja = (rr2 < 2) ? jm0 : jm1;
                        bool okd = (j <= ia) || ((ia >= fi) && covr && (j >= li));
                        d[rr2] = okd ? fmaf(sp_l2, (float)(j - ja), d[rr2]) : -1e30f;
                        int ib = (rr2 < 2) ? i2 : i3;
                        int jb = (rr2 < 2) ? jm2 : jm3;
                        bool oke = (j <= ib) || ((ib >= fi) && covr && (j >= li));
                        e[rr2] = oke ? fmaf(sp_l2, (float)(j - jb), e[rr2]) : -1e30f;
                    }
                }
                pA0[ni] = packh2(d[0], d[1]);
                pA1[ni] = packh2(d[2], d[3]);
                pB0[ni] = packh2(e[0], e[1]);
                pB1[ni] = packh2(e[2], e[3]);
            }
        }

        // row maxes over packed scores
        __half2 hA0 = pA0[0], hA1 = pA1[0], hB0 = pB0[0], hB1 = pB1[0];
#pragma unroll
        for (int ni = 1; ni < 16; ni++) {
            hA0 = __hmax2(hA0, pA0[ni]);
            hA1 = __hmax2(hA1, pA1[ni]);
            hB0 = __hmax2(hB0, pB0[ni]);
            hB1 = __hmax2(hB1, pB1[ni]);
        }
        float rp0 = fmaxf(__low2float(hA0), __high2float(hA0));
        float rp1 = fmaxf(__low2float(hA1), __high2float(hA1));
        float rp2 = fmaxf(__low2float(hB0), __high2float(hB0));
        float rp3 = fmaxf(__low2float(hB1), __high2float(hB1));
        rp0 = fmaxf(rp0, __shfl_xor_sync(0xffffffffu, rp0, 1));
        rp0 = fmaxf(rp0, __shfl_xor_sync(0xffffffffu, rp0, 2));
        rp1 = fmaxf(rp1, __shfl_xor_sync(0xffffffffu, rp1, 1));
        rp1 = fmaxf(rp1, __shfl_xor_sync(0xffffffffu, rp1, 2));
        rp2 = fmaxf(rp2, __shfl_xor_sync(0xffffffffu, rp2, 1));
        rp2 = fmaxf(rp2, __shfl_xor_sync(0xffffffffu, rp2, 2));
        rp3 = fmaxf(rp3, __shfl_xor_sync(0xffffffffu, rp3, 1));
        rp3 = fmaxf(rp3, __shfl_xor_sync(0xffffffffu, rp3, 2));
        const float mn0 = fmaxf(m0, rp0 + off0);
        const float mn1 = fmaxf(m1, rp1 + off1);
        const float mn2 = fmaxf(m2, rp2 + off2);
        const float mn3 = fmaxf(m3, rp3 + off3);
        const float c0 = exp2f(m0 - mn0), c1 = exp2f(m1 - mn1);
        const float c2 = exp2f(m2 - mn2), c3 = exp2f(m3 - mn3);
        m0 = mn0; m1 = mn1; m2 = mn2; m3 = mn3;
#pragma unroll
        for (int ni = 0; ni < 16; ni++) {
            o0[ni][0] *= c0; o0[ni][1] *= c0; o0[ni][2] *= c1; o0[ni][3] *= c1;
            o1[ni][0] *= c2; o1[ni][1] *= c2; o1[ni][2] *= c3; o1[ni][3] *= c3;
        }
        ol0[0] *= c0; ol0[1] *= c0; ol0[2] *= c1; ol0[3] *= c1;
        ol1[0] *= c2; ol1[1] *= c2; ol1[2] *= c3; ol1[3] *= c3;

        // P = exp2(packed - (m - off)) in f16x2
        const __half2 mb0 = __float2half2_rn(mn0 - off0);
        const __half2 mb1 = __float2half2_rn(mn1 - off1);
        const __half2 mb2 = __float2half2_rn(mn2 - off2);
        const __half2 mb3 = __float2half2_rn(mn3 - off3);
#pragma unroll
        for (int ni = 0; ni < 16; ni++) {
            pA0[ni] = h2exp2(__hsub2(pA0[ni], mb0));
            pA1[ni] = h2exp2(__hsub2(pA1[ni], mb1));
            pB0[ni] = h2exp2(__hsub2(pB0[ni], mb2));
            pB1[ni] = h2exp2(__hsub2(pB1[ni], mb3));
        }

        // PV (f16): V fragments loaded once, used for both A-tiles
        const uint32_t vrow = vsb + l15 * 256;
#pragma unroll
        for (int ks = 0; ks < 8; ks++) {
            uint32_t pa0[4] = {*(uint32_t*)&pA0[2 * ks], *(uint32_t*)&pA1[2 * ks],
                               *(uint32_t*)&pA0[2 * ks + 1], *(uint32_t*)&pA1[2 * ks + 1]};
            uint32_t pa1[4] = {*(uint32_t*)&pB0[2 * ks], *(uint32_t*)&pB1[2 * ks],
                               *(uint32_t*)&pB0[2 * ks + 1], *(uint32_t*)&pB1[2 * ks + 1]};
            mma16816h(ol0, pa0, bones);
            mma16816h(ol1, pa1, bones);
            const uint32_t kofs = vrow + ks * 4096;
#pragma unroll
            for (int ni2 = 0; ni2 < 8; ni2++) {
                uint32_t rr[4];
                ldsm4t(rr, kofs + (((ni2 * 2 + lhi) ^ l15) << 4));
                uint32_t b0[2] = {rr[0], rr[1]};
                uint32_t b1[2] = {rr[2], rr[3]};
                mma16816h(o0[2 * ni2], pa0, b0);
                mma16816h(o0[2 * ni2 + 1], pa0, b1);
                mma16816h(o1[2 * ni2], pa1, b0);
                mma16816h(o1[2 * ni2 + 1], pa1, b1);
            }
        }
        __syncthreads();
    }

    const float inv0 = 1.f / ol0[0], inv1 = 1.f / ol0[2];
    const float inv2 = 1.f / ol1[0], inv3 = 1.f / ol1[2];
#pragma unroll
    for (int ni = 0; ni < 16; ni++) {
        int col = 1024 + h * 128 + ni * 8 + tig * 2;
        *(__nv_bfloat162*)&concat[((size_t)(b * SS) + i0) * EXPD + col] =
            __floats2bfloat162_rn(o0[ni][0] * inv0, o0[ni][1] * inv0);
        *(__nv_bfloat162*)&concat[((size_t)(b * SS) + i1) * EXPD + col] =
            __floats2bfloat162_rn(o0[ni][2] * inv1, o0[ni][3] * inv1);
        *(__nv_bfloat162*)&concat[((size_t)(b * SS) + i2) * EXPD + col] =
            __floats2bfloat162_rn(o1[ni][0] * inv2, o1[ni][1] * inv2);
        *(__nv_bfloat162*)&concat[((size_t)(b * SS) + i3) * EXPD + col] =
            __floats2bfloat162_rn(o1[ni][2] * inv3, o1[ni][3] * inv3);
    }
}

// ---------------- launch ----------------
extern "C" void kernel_launch(void* const* d_in, const int* in_sizes, int n_in,
                              void* d_out, int out_size) {
    const float* x = (const float*)d_in[0];
    const float* norm_w = (const float*)d_in[1];
    const float* expand_w = (const float*)d_in[2];
    const float* project_w = (const float*)d_in[3];
    const float* pbm = (const float*)d_in[4];
    const int* fi = (const int*)d_in[5];
    const int* li = (const int*)d_in[6];
    float* out = (float*)d_out;

    void *p_xn, *p_qk, *p_concat, *p_v, *p_wexp, *p_wproj;
    cudaGetSymbolAddress(&p_xn, g_xn);
    cudaGetSymbolAddress(&p_qk, g_qk);
    cudaGetSymbolAddress(&p_concat, g_concat);
    cudaGetSymbolAddress(&p_v, g_v);
    cudaGetSymbolAddress(&p_wexp, g_wexp);
    cudaGetSymbolAddress(&p_wproj, g_wproj);
    __nv_bfloat16* xn = (__nv_bfloat16*)p_xn;
    __nv_bfloat16* qk = (__nv_bfloat16*)p_qk;
    __nv_bfloat16* concat = (__nv_bfloat16*)p_concat;
    __half* vb = (__half*)p_v;
    __nv_bfloat16* wexp = (__nv_bfloat16*)p_wexp;
    __nv_bfloat16* wproj = (__nv_bfloat16*)p_wproj;

    cudaFuncSetAttribute(gemm_bf16<0, 1024>, cudaFuncAttributeMaxDynamicSharedMemorySize, GSMEM_BYTES);
    cudaFuncSetAttribute(gemm_bf16<1, 2048>, cudaFuncAttributeMaxDynamicSharedMemorySize, GSMEM_BYTES);
    cudaFuncSetAttribute(attn_kernel, cudaFuncAttributeMaxDynamicSharedMemorySize, ATT_SMEM);

    // merged weight convert
    cvt_all_kernel<<<(WEXP4 + WPROJ4 + 255) / 256, 256>>>(expand_w, project_w, wexp, wproj);

    // layernorm
    ln_kernel<<<NROWS, 256>>>(x, norm_w, xn);

    // expand GEMM fused with geglu
    gemm_bf16<0, 1024><<<dim3(EOUT / 128, NROWS / 128), 256, GSMEM_BYTES>>>(
        xn, wexp, qk, concat, vb, nullptr, nullptr);

    // attention (q-tile 128, 128-thread CTAs, occ 2) -> concat[:, 1024:2048]
    attn_kernel<<<dim3(SS / 128, BB * HH), 128, ATT_SMEM>>>(qk, vb, concat, pbm, fi, li);

    // project GEMM + residual
    gemm_bf16<1, 2048><<<dim3(DD / 128, NROWS / 128), 256, GSMEM_BYTES>>>(
        concat, wproj, nullptr, nullptr, nullptr, x, out);
}